// round 16
// baseline (speedup 1.0000x reference)
#include <cuda_runtime.h>

// EM-routing capsule layer. B=64, S=14, I=32 -> N=6272/batch, C=10, D=16, 3 iters.
// Pass 0 linearized. R16:
//  (a) pass0 p-split: warps 0-4 accumulate p={0,1} Gram half, warps 5-9 p={2,3};
//      ~40 accumulators/thread -> occupancy 2, grid 256 (pass0 ~2x faster).
//  (b) accum double-step: FINISH is STATELESS (recomputes votes from the ring-8
//      tile, zz ring-4, act ring-8) so 2 spatial steps share one barrier
//      (49 -> 25 barriers) with no carried register bank (avoids R7's spills).

#define BB   64
#define SSQ  196
#define II   32
#define CCL  10
#define EPSf 1e-9f
#define L2E  1.4426950408889634f

typedef unsigned long long u64;

__device__ float g0[256 * 10 * 69 * 32];        // pass0 per-(cta,warp) slabs (half-fields)
__device__ float g_partial[256 * CCL * 34];     // per (b*4+sl, c): [0]=rsum [1..16]=sv [17..32]=sv2
__device__ float g_stats[BB * CCL * 34];        // per (b,c): [0..15]=nms [16..31]=siv [32]=cst (log2)

__device__ __forceinline__ u64 pack2(float lo, float hi) {
    u64 r; asm("mov.b64 %0,{%1,%2};" : "=l"(r) : "f"(lo), "f"(hi)); return r;
}
__device__ __forceinline__ void unpack2(u64 v, float& lo, float& hi) {
    asm("mov.b64 {%0,%1},%2;" : "=f"(lo), "=f"(hi) : "l"(v));
}
__device__ __forceinline__ u64 fma2(u64 a, u64 b, u64 c) {
    u64 d; asm("fma.rn.f32x2 %0,%1,%2,%3;" : "=l"(d) : "l"(a), "l"(b), "l"(c)); return d;
}
__device__ __forceinline__ u64 add2(u64 a, u64 b) {
    u64 d; asm("add.rn.f32x2 %0,%1,%2;" : "=l"(d) : "l"(a), "l"(b)); return d;
}
__device__ __forceinline__ u64 mul2(u64 a, u64 b) {
    u64 d; asm("mul.rn.f32x2 %0,%1,%2;" : "=l"(d) : "l"(a), "l"(b)); return d;
}
__device__ __forceinline__ float ex2f(float x) {
    float y; asm("ex2.approx.f32 %0,%1;" : "=f"(y) : "f"(x)); return y;
}
__device__ __forceinline__ void cp16(unsigned dst, const void* src) {
    asm volatile("cp.async.cg.shared.global [%0], [%1], 16;" :: "r"(dst), "l"(src));
}
__device__ __forceinline__ void cp4(unsigned dst, const void* src) {
    asm volatile("cp.async.ca.shared.global [%0], [%1], 4;" :: "r"(dst), "l"(src));
}
#define CP_COMMIT() asm volatile("cp.async.commit_group;" ::: "memory")
#define CP_WAIT1()  asm volatile("cp.async.wait_group 1;"  ::: "memory")

// ---------------- pass 0: p-split linear/quadratic reduction ----------------
__global__ __launch_bounds__(320, 2)
void pass0_kernel(const float* __restrict__ pose, const float* __restrict__ act)
{
    const int cta = blockIdx.x, b = cta >> 2, qt = cta & 3;
    const int w = threadIdx.x >> 5, i = threadIdx.x & 31;
    const int ph  = (w >= 5);            // 0: p={0,1}, 1: p={2,3}
    const int wsl = w - (ph ? 5 : 0);

    float aP[8], G[20];
    float X1[4], X2[4], ra = 0.f, rc1 = 0.f, rc2 = 0.f, rq1 = 0.f, rq2 = 0.f;
    #pragma unroll
    for (int f = 0; f < 8; f++) aP[f] = 0.f;
    #pragma unroll
    for (int f = 0; f < 20; f++) G[f] = 0.f;
    #pragma unroll
    for (int f = 0; f < 4; f++) { X1[f] = 0.f; X2[f] = 0.f; }

    for (int sl = wsl; sl < 49; sl += 5) {
        const int s  = qt * 49 + sl;
        const int h  = s / 14;
        const int wx = s - h * 14;
        const float cr = (h  + 0.5f) * (1.0f / 14.0f);
        const float cw = (wx + 0.5f) * (1.0f / 14.0f);

        const size_t nidx = ((size_t)(b * SSQ + s) * II + i);
        const float4* pv = reinterpret_cast<const float4*>(pose + nidx * 16) + ph * 2;
        float p8[8];
        {
            float4 t0 = pv[0], t1 = pv[1];
            p8[0] = t0.x; p8[1] = t0.y; p8[2] = t0.z; p8[3] = t0.w;
            p8[4] = t1.x; p8[5] = t1.y; p8[6] = t1.z; p8[7] = t1.w;
        }
        const float a = act[nidx];

        #pragma unroll
        for (int lp = 0; lp < 2; lp++) {
            float t0 = a * p8[lp*4+0], t1 = a * p8[lp*4+1];
            float t2 = a * p8[lp*4+2], t3 = a * p8[lp*4+3];
            aP[lp*4+0] += t0; aP[lp*4+1] += t1; aP[lp*4+2] += t2; aP[lp*4+3] += t3;
            float* Gp = G + lp * 10;
            Gp[0] = fmaf(t0, p8[lp*4+0], Gp[0]);
            Gp[1] = fmaf(t0, p8[lp*4+1], Gp[1]);
            Gp[2] = fmaf(t0, p8[lp*4+2], Gp[2]);
            Gp[3] = fmaf(t0, p8[lp*4+3], Gp[3]);
            Gp[4] = fmaf(t1, p8[lp*4+1], Gp[4]);
            Gp[5] = fmaf(t1, p8[lp*4+2], Gp[5]);
            Gp[6] = fmaf(t1, p8[lp*4+3], Gp[6]);
            Gp[7] = fmaf(t2, p8[lp*4+2], Gp[7]);
            Gp[8] = fmaf(t2, p8[lp*4+3], Gp[8]);
            Gp[9] = fmaf(t3, p8[lp*4+3], Gp[9]);
        }
        if (!ph) {
            ra += a;
            const float acr = a * cr, acw = a * cw;
            rc1 += acr; rc2 += acw;
            rq1 = fmaf(acr, cr, rq1); rq2 = fmaf(acw, cw, rq2);
            #pragma unroll
            for (int q = 0; q < 4; q++) {
                X1[q] = fmaf(acr, p8[q], X1[q]);
                X2[q] = fmaf(acw, p8[q], X2[q]);
            }
        }
    }

    float* o = g0 + (size_t)(cta * 10 + w) * 69 * 32 + i;
    if (!ph) {
        #pragma unroll
        for (int f = 0; f < 8; f++)  o[f * 32] = aP[f];
        #pragma unroll
        for (int f = 0; f < 20; f++) o[(16 + f) * 32] = G[f];
        o[56 * 32] = ra;
        o[57 * 32] = rc1; o[58 * 32] = rc2;
        o[59 * 32] = rq1; o[60 * 32] = rq2;
        #pragma unroll
        for (int f = 0; f < 4; f++) { o[(61 + f) * 32] = X1[f]; o[(65 + f) * 32] = X2[f]; }
    } else {
        #pragma unroll
        for (int f = 0; f < 8; f++)  o[(8 + f) * 32] = aP[f];
        #pragma unroll
        for (int f = 0; f < 20; f++) o[(36 + f) * 32] = G[f];
    }
}

// ---------------- pass 0 stats ----------------
__global__ __launch_bounds__(320, 1)
void stats0_kernel(const float* __restrict__ wt,
                   const float* __restrict__ beta_v,
                   const float* __restrict__ beta_a)
{
    __shared__ float sm[32][72];
    const int b = blockIdx.x, tid = threadIdx.x;

    for (int t = tid; t < 32 * 69; t += 320) {
        const int i = t / 69, f = t - i * 69;
        const bool ph0 = (f < 8) || (f >= 16 && f < 36) || (f >= 56);
        const int ww0 = ph0 ? 0 : 5;
        float s = 0.f;
        #pragma unroll
        for (int qq = 0; qq < 4; qq++) {
            const size_t base = (size_t)(((b * 4 + qq) * 10 + ww0)) * 69 * 32 + f * 32 + i;
            #pragma unroll
            for (int ww = 0; ww < 5; ww++) s += g0[base + (size_t)ww * 69 * 32];
        }
        sm[i][f] = s;
    }
    __syncthreads();

    if (tid < 160) {
        const int c = tid >> 4, d = tid & 15, p = d >> 2, r = d & 3;
        float RA = 0.f, RC = 0.f, RQ = 0.f, Sv = 0.f, Sv2 = 0.f, Cr = 0.f;
        for (int i = 0; i < 32; i++) {
            const float* g = sm[i];
            const float* wr = wt + (i * CCL + c) * 16;
            const float W0 = wr[0*4+r], W1 = wr[1*4+r], W2 = wr[2*4+r], W3 = wr[3*4+r];
            const float* ap = g + p * 4;
            Sv += ap[0]*W0 + ap[1]*W1 + ap[2]*W2 + ap[3]*W3;
            const float* Gp = g + 16 + p * 10;
            Sv2 += W0*W0*Gp[0] + W1*W1*Gp[4] + W2*W2*Gp[7] + W3*W3*Gp[9]
                 + 2.f*(W0*W1*Gp[1] + W0*W2*Gp[2] + W0*W3*Gp[3]
                      + W1*W2*Gp[5] + W1*W3*Gp[6] + W2*W3*Gp[8]);
            RA += g[56];
            if (d == 0) { RC += g[57]; RQ += g[59]; Cr += W0*g[61]+W1*g[62]+W2*g[63]+W3*g[64]; }
            else if (d == 1) { RC += g[58]; RQ += g[60]; Cr += W0*g[65]+W1*g[66]+W2*g[67]+W3*g[68]; }
        }
        float coordm = (d == 0 || d == 1) ? RC : 0.f;
        float coordv = (d == 0 || d == 1) ? (2.f * Cr + RQ) : 0.f;
        float mean = (Sv + coordm) / RA;
        float var  = fmaxf((Sv2 + coordv) / RA - mean * mean, 0.f);
        float lg   = __logf(sqrtf(var) + EPSf);
        float rr_sum = RA * 0.1f;
        float cost = (beta_v[c] + lg) * rr_sum, lgs = lg;
        #pragma unroll
        for (int off = 8; off; off >>= 1) {
            cost += __shfl_xor_sync(0xffffffffu, cost, off, 16);
            lgs  += __shfl_xor_sync(0xffffffffu, lgs,  off, 16);
        }
        float oact = 1.f / (1.f + __expf(-(beta_a[c] - cost)));   // invT = 1
        float siv  = sqrtf(L2E / (2.f * var + EPSf));
        float* st = g_stats + (b * CCL + c) * 34;
        st[d]      = -mean * siv;
        st[16 + d] = siv;
        if (d == 0) st[32] = (__logf(oact + EPSf) - lgs) * L2E;
    }
}

// ---------------- routing passes 1 and 2 (double-step, stateless FINISH) ----------------

#define VOTES(K, V2) {                                                         \
    const float2 _cc2 = s_coord[(K)];                                          \
    V2[0] = pack2(_cc2.x, _cc2.y);                                             \
    _Pragma("unroll")                                                          \
    for (int _j = 1; _j < 8; _j++) V2[_j] = 0ULL;                              \
    _Pragma("unroll")                                                          \
    for (int _p = 0; _p < 4; _p++) {                                           \
        float4 _tp = s_tile[(K) & 7][sxp[_p]];                                 \
        u64 _pp;                                                               \
        _pp = pack2(_tp.x, _tp.x);                                             \
        V2[_p*2+0] = fma2(_pp, W2[0][0], V2[_p*2+0]);                          \
        V2[_p*2+1] = fma2(_pp, W2[0][1], V2[_p*2+1]);                          \
        _pp = pack2(_tp.y, _tp.y);                                             \
        V2[_p*2+0] = fma2(_pp, W2[1][0], V2[_p*2+0]);                          \
        V2[_p*2+1] = fma2(_pp, W2[1][1], V2[_p*2+1]);                          \
        _pp = pack2(_tp.z, _tp.z);                                             \
        V2[_p*2+0] = fma2(_pp, W2[2][0], V2[_p*2+0]);                          \
        V2[_p*2+1] = fma2(_pp, W2[2][1], V2[_p*2+1]);                          \
        _pp = pack2(_tp.w, _tp.w);                                             \
        V2[_p*2+0] = fma2(_pp, W2[3][0], V2[_p*2+0]);                          \
        V2[_p*2+1] = fma2(_pp, W2[3][1], V2[_p*2+1]);                          \
    }                                                                          \
}

// votes -> zz -> store (no accumulation, no carried state)
#define COMPUTE_ZZ(K) {                                                        \
    u64 _v[8];                                                                 \
    VOTES(K, _v);                                                              \
    u64 _az0 = 0ULL, _az1 = 0ULL;                                              \
    _Pragma("unroll")                                                          \
    for (int _j = 0; _j < 8; _j++) {                                           \
        u64 _nm, _sviv;                                                        \
        asm volatile("ld.shared.v2.b64 {%0,%1},[%2];"                          \
                     : "=l"(_nm), "=l"(_sviv) : "r"(stat_base + 16u * _j));    \
        u64 _t = fma2(_v[_j], _sviv, _nm);                                     \
        if (_j & 1) _az1 = fma2(_t, _t, _az1);                                 \
        else        _az0 = fma2(_t, _t, _az0);                                 \
    }                                                                          \
    float _l0,_h0,_l1,_h1; unpack2(_az0,_l0,_h0); unpack2(_az1,_l1,_h1);       \
    s_zz[(K) & 3][czz + lane] = cstc - ((_l0 + _l1) + (_h0 + _h1));            \
}

// stateless finish: recompute votes from resident tile, softmax, accumulate
#define FINISH_R(K) {                                                          \
    u64 _v[8];                                                                 \
    VOTES(K, _v);                                                              \
    const float _zc = s_zz[(K) & 3][czz + lane];                               \
    const float _a  = s_actr[(K) & 7][lane];                                   \
    const float* _zr = &s_zz[(K) & 3][lane];                                   \
    float _Z0 = 0.f, _Z1 = 0.f;                                                \
    _Pragma("unroll")                                                          \
    for (int _j = 0; _j < 10; _j++) {                                          \
        float _e = ex2f(_zr[_j * 32] - _zc);                                   \
        if (_j & 1) _Z1 += _e; else _Z0 += _e;                                 \
    }                                                                          \
    const float _rrp = __fdividef(_a, _Z0 + _Z1);                              \
    rsum += _rrp;                                                              \
    const u64 _rr2 = pack2(_rrp, _rrp);                                        \
    _Pragma("unroll")                                                          \
    for (int _j = 0; _j < 8; _j++) {                                           \
        const u64 _rv = mul2(_rr2, _v[_j]);                                    \
        sv[_j]  = add2(sv[_j], _rv);                                           \
        sv2[_j] = fma2(_rv, _v[_j], sv2[_j]);                                  \
    }                                                                          \
}

// issue tiles K, K+1 (guarded) as one cp.async group
#define ISSUE2(K) {                                                            \
    if (tid < 128) {                                                           \
        if ((K)     < 49) cp16(my_dst  + (unsigned)((((K))     & 7) << 11),    \
                               psrc + (K) * 128 + tid);                        \
        if ((K) + 1 < 49) cp16(my_dst  + (unsigned)((((K) + 1) & 7) << 11),    \
                               psrc + ((K) + 1) * 128 + tid);                  \
    } else if (tid < 160) {                                                    \
        if ((K)     < 49) cp4(my_dsta + (unsigned)((((K))     & 7) << 7),      \
                              asrc + (K) * II + (tid - 128));                  \
        if ((K) + 1 < 49) cp4(my_dsta + (unsigned)((((K) + 1) & 7) << 7),      \
                              asrc + ((K) + 1) * II + (tid - 128));            \
    }                                                                          \
    CP_COMMIT();                                                               \
}

template<int IT>
__global__ __launch_bounds__(320, 2)
void accum_kernel(const float* __restrict__ pose,
                  const float* __restrict__ act,
                  const float* __restrict__ wt,
                  const float* __restrict__ beta_v,
                  const float* __restrict__ beta_a)
{
    __shared__ float4 s_tile[8][128];                  // ring-8 tiles (16 KB)
    __shared__ float  s_actr[8][32];
    __shared__ float  s_zz[4][320];                    // ring-4 zz buffers
    __shared__ __align__(16) float s_stat[CCL][8][4];
    __shared__ float  s_cst[CCL];
    __shared__ float2 s_coord[49];

    const int cta = blockIdx.x, b = cta >> 2, sl = cta & 3;
    const int tid = threadIdx.x, c = tid >> 5, lane = tid & 31;
    const int s0 = sl * 49;
    const int czz = c * 32;

    // ---- stats into smem ----
    if (tid < 160) {
        const int cc = tid >> 4, d = tid & 15;
        float nmsv, sivv, cstv = 0.f;
        if (IT == 1) {
            const float* st = g_stats + (b * CCL + cc) * 34;
            nmsv = st[d]; sivv = st[16 + d];
            if (d == 0) cstv = st[32];
        } else {
            float rsum0 = 0.f, sva = 0.f, sv2a = 0.f;
            #pragma unroll
            for (int q = 0; q < 4; q++) {
                const float* p = g_partial + ((b * 4 + q) * CCL + cc) * 34;
                rsum0 += p[0]; sva += p[1 + d]; sv2a += p[17 + d];
            }
            float mean = sva / rsum0;
            float var  = fmaxf(sv2a / rsum0 - mean * mean, 0.f);
            float lg   = __logf(sqrtf(var) + EPSf);
            float cost = (beta_v[cc] + lg) * rsum0, lgs = lg;
            #pragma unroll
            for (int off = 8; off; off >>= 1) {
                cost += __shfl_xor_sync(0xffffffffu, cost, off, 16);
                lgs  += __shfl_xor_sync(0xffffffffu, lgs,  off, 16);
            }
            float oact = 1.f / (1.f + __expf(-2.0f * (beta_a[cc] - cost)));  // invT = 2
            sivv = sqrtf(L2E / (2.f * var + EPSf));
            nmsv = -mean * sivv;
            if (d == 0) cstv = (__logf(oact + EPSf) - lgs) * L2E;
        }
        s_stat[cc][d >> 1][d & 1]       = nmsv;
        s_stat[cc][d >> 1][2 + (d & 1)] = sivv;
        if (d == 0) s_cst[cc] = cstv;
    } else if (tid >= 256 && tid < 305) {
        const int s = s0 + (tid - 256);
        const int h = s / 14, wx = s - h * 14;
        s_coord[tid - 256] = make_float2((h + 0.5f) * (1.0f/14.0f), (wx + 0.5f) * (1.0f/14.0f));
    }

    // ---- cp.async staging ----
    const float4* pose4 = reinterpret_cast<const float4*>(pose);
    const size_t nb0 = ((size_t)(b * SSQ) + s0) * II;
    const float4* psrc = pose4 + nb0 * 4;
    const float*  asrc = act + nb0;

    const unsigned tile_smem = (unsigned)__cvta_generic_to_shared(s_tile);
    const unsigned act_smem  = (unsigned)__cvta_generic_to_shared(s_actr);
    unsigned my_dst = 0, my_dsta = 0;
    if (tid < 128) {
        const int sx = tid ^ ((tid >> 3) & 7);
        my_dst = tile_smem + (unsigned)(sx * 16);
    } else if (tid < 160) {
        my_dsta = act_smem + (unsigned)((tid - 128) * 4);
    }

    ISSUE2(0);          // group: tiles 0,1
    ISSUE2(2);          // group: tiles 2,3
    CP_WAIT1();         // tiles 0,1 complete
    __syncthreads();

    // ---- per-warp constants ----
    u64 W2[4][2];
    {
        const float* wr = wt + (lane * CCL + c) * 16;
        #pragma unroll
        for (int q = 0; q < 4; q++) {
            W2[q][0] = pack2(wr[q*4+0], wr[q*4+1]);
            W2[q][1] = pack2(wr[q*4+2], wr[q*4+3]);
        }
    }
    const float cstc = s_cst[c];
    const unsigned stat_base = (unsigned)__cvta_generic_to_shared(&s_stat[c][0][0]);

    int sxp[4];
    #pragma unroll
    for (int p = 0; p < 4; p++) {
        const int idx = lane * 4 + p;
        sxp[p] = idx ^ ((idx >> 3) & 7);
    }

    u64 sv[8], sv2[8];
    #pragma unroll
    for (int j = 0; j < 8; j++) { sv[j] = 0ULL; sv2[j] = 0ULL; }
    float rsum = 0.f;

    // ---- main loop: 2 steps per barrier ----
    #pragma unroll 1
    for (int k = 0; k < 48; k += 2) {
        ISSUE2(k + 4);
        if (k >= 2) { FINISH_R(k - 2); FINISH_R(k - 1); }
        COMPUTE_ZZ(k);
        COMPUTE_ZZ(k + 1);
        CP_WAIT1();         // tiles k+2,k+3 ready
        __syncthreads();    // zz(k,k+1) visible; tiles safe
    }
    // epilogue: step 48 + remaining finishes
    COMPUTE_ZZ(48);
    FINISH_R(46); FINISH_R(47);
    __syncthreads();
    FINISH_R(48);

    // reduce over the 32 lanes (capsule i)
    #pragma unroll
    for (int off = 16; off; off >>= 1) {
        rsum += __shfl_xor_sync(0xffffffffu, rsum, off);
        #pragma unroll
        for (int j = 0; j < 8; j++) {
            sv[j]  = add2(sv[j],  __shfl_xor_sync(0xffffffffu, sv[j],  off));
            sv2[j] = add2(sv2[j], __shfl_xor_sync(0xffffffffu, sv2[j], off));
        }
    }
    if (lane == 0) {
        float* o = g_partial + (cta * CCL + c) * 34;
        o[0] = rsum;
        #pragma unroll
        for (int j = 0; j < 8; j++) {
            float lo, hi;
            unpack2(sv[j],  lo, hi); o[1  + 2*j] = lo; o[2  + 2*j] = hi;
            unpack2(sv2[j], lo, hi); o[17 + 2*j] = lo; o[18 + 2*j] = hi;
        }
    }
}

// ---------------- final output ----------------
__global__ __launch_bounds__(160)
void finalize_out(const float* __restrict__ beta_v,
                  const float* __restrict__ beta_a,
                  float* __restrict__ out)
{
    const int b = blockIdx.x;
    const int c = threadIdx.x >> 4;
    const int d = threadIdx.x & 15;

    float rsum = 0.f, sv = 0.f, sv2 = 0.f;
    #pragma unroll
    for (int q = 0; q < 4; q++) {
        const float* p = g_partial + ((b * 4 + q) * CCL + c) * 34;
        rsum += p[0]; sv += p[1 + d]; sv2 += p[17 + d];
    }
    float mean = sv / rsum;
    float var  = fmaxf(sv2 / rsum - mean * mean, 0.f);
    float lg   = __logf(sqrtf(var) + EPSf);
    float cost = (beta_v[c] + lg) * rsum;
    #pragma unroll
    for (int off = 8; off; off >>= 1)
        cost += __shfl_xor_sync(0xffffffffu, cost, off, 16);

    float oact = 1.f / (1.f + __expf(-3.0f * (beta_a[c] - cost)));   // invT = 3

    out[(b * CCL + c) * 16 + d] = mean;
    if (d == 0) out[BB * CCL * 16 + b * CCL + c] = oact;
}

extern "C" void kernel_launch(void* const* d_in, const int* in_sizes, int n_in,
                              void* d_out, int out_size)
{
    const float* pose = (const float*)d_in[0];
    const float* act  = (const float*)d_in[1];
    const float* w    = (const float*)d_in[2];
    const float* bv   = (const float*)d_in[3];
    const float* ba   = (const float*)d_in[4];
    float* out = (float*)d_out;

    pass0_kernel <<<256, 320>>>(pose, act);
    stats0_kernel<<<64, 320>>>(w, bv, ba);
    accum_kernel<1><<<256, 320>>>(pose, act, w, bv, ba);
    accum_kernel<2><<<256, 320>>>(pose, act, w, bv, ba);
    finalize_out <<<64, 160>>>(bv, ba, out);
}

// round 17
// speedup vs baseline: 1.2052x; 1.2052x over previous
#include <cuda_runtime.h>

// EM-routing capsule layer. B=64, S=14, I=32 -> N=6272/batch, C=10, D=16, 3 iters.
// Pass 0 linearized (p-split, occupancy 2). Passes 1-2 = R6 structure (best
// measured) + transposed conflict-free zz + spread float2 prefetch.
// finalize fused into accum<2> via fence+atomic last-CTA-per-batch pattern.

#define BB   64
#define SSQ  196
#define II   32
#define CCL  10
#define EPSf 1e-9f
#define L2E  1.4426950408889634f

typedef unsigned long long u64;

__device__ float g0[256 * 10 * 69 * 32];        // pass0 per-(cta,warp) slabs (half-fields)
__device__ float g_partial[256 * CCL * 34];     // per (b*4+sl, c): [0]=rsum [1..16]=sv [17..32]=sv2
__device__ float g_stats[BB * CCL * 34];        // per (b,c): [0..15]=nms [16..31]=siv [32]=cst (log2)
__device__ int   g_cnt[BB];                     // last-CTA counters (zero at rest)

__device__ __forceinline__ u64 pack2(float lo, float hi) {
    u64 r; asm("mov.b64 %0,{%1,%2};" : "=l"(r) : "f"(lo), "f"(hi)); return r;
}
__device__ __forceinline__ void unpack2(u64 v, float& lo, float& hi) {
    asm("mov.b64 {%0,%1},%2;" : "=f"(lo), "=f"(hi) : "l"(v));
}
__device__ __forceinline__ u64 fma2(u64 a, u64 b, u64 c) {
    u64 d; asm("fma.rn.f32x2 %0,%1,%2,%3;" : "=l"(d) : "l"(a), "l"(b), "l"(c)); return d;
}
__device__ __forceinline__ u64 add2(u64 a, u64 b) {
    u64 d; asm("add.rn.f32x2 %0,%1,%2;" : "=l"(d) : "l"(a), "l"(b)); return d;
}
__device__ __forceinline__ u64 mul2(u64 a, u64 b) {
    u64 d; asm("mul.rn.f32x2 %0,%1,%2;" : "=l"(d) : "l"(a), "l"(b)); return d;
}
__device__ __forceinline__ float ex2f(float x) {
    float y; asm("ex2.approx.f32 %0,%1;" : "=f"(y) : "f"(x)); return y;
}

// ---------------- pass 0: p-split linear/quadratic reduction ----------------
__global__ __launch_bounds__(320, 2)
void pass0_kernel(const float* __restrict__ pose, const float* __restrict__ act)
{
    const int cta = blockIdx.x, b = cta >> 2, qt = cta & 3;
    const int w = threadIdx.x >> 5, i = threadIdx.x & 31;
    const int ph  = (w >= 5);            // 0: p={0,1}, 1: p={2,3}
    const int wsl = w - (ph ? 5 : 0);

    float aP[8], G[20];
    float X1[4], X2[4], ra = 0.f, rc1 = 0.f, rc2 = 0.f, rq1 = 0.f, rq2 = 0.f;
    #pragma unroll
    for (int f = 0; f < 8; f++) aP[f] = 0.f;
    #pragma unroll
    for (int f = 0; f < 20; f++) G[f] = 0.f;
    #pragma unroll
    for (int f = 0; f < 4; f++) { X1[f] = 0.f; X2[f] = 0.f; }

    for (int sl = wsl; sl < 49; sl += 5) {
        const int s  = qt * 49 + sl;
        const int h  = s / 14;
        const int wx = s - h * 14;
        const float cr = (h  + 0.5f) * (1.0f / 14.0f);
        const float cw = (wx + 0.5f) * (1.0f / 14.0f);

        const size_t nidx = ((size_t)(b * SSQ + s) * II + i);
        const float4* pv = reinterpret_cast<const float4*>(pose + nidx * 16) + ph * 2;
        float p8[8];
        {
            float4 t0 = pv[0], t1 = pv[1];
            p8[0] = t0.x; p8[1] = t0.y; p8[2] = t0.z; p8[3] = t0.w;
            p8[4] = t1.x; p8[5] = t1.y; p8[6] = t1.z; p8[7] = t1.w;
        }
        const float a = act[nidx];

        #pragma unroll
        for (int lp = 0; lp < 2; lp++) {
            float t0 = a * p8[lp*4+0], t1 = a * p8[lp*4+1];
            float t2 = a * p8[lp*4+2], t3 = a * p8[lp*4+3];
            aP[lp*4+0] += t0; aP[lp*4+1] += t1; aP[lp*4+2] += t2; aP[lp*4+3] += t3;
            float* Gp = G + lp * 10;
            Gp[0] = fmaf(t0, p8[lp*4+0], Gp[0]);
            Gp[1] = fmaf(t0, p8[lp*4+1], Gp[1]);
            Gp[2] = fmaf(t0, p8[lp*4+2], Gp[2]);
            Gp[3] = fmaf(t0, p8[lp*4+3], Gp[3]);
            Gp[4] = fmaf(t1, p8[lp*4+1], Gp[4]);
            Gp[5] = fmaf(t1, p8[lp*4+2], Gp[5]);
            Gp[6] = fmaf(t1, p8[lp*4+3], Gp[6]);
            Gp[7] = fmaf(t2, p8[lp*4+2], Gp[7]);
            Gp[8] = fmaf(t2, p8[lp*4+3], Gp[8]);
            Gp[9] = fmaf(t3, p8[lp*4+3], Gp[9]);
        }
        if (!ph) {
            ra += a;
            const float acr = a * cr, acw = a * cw;
            rc1 += acr; rc2 += acw;
            rq1 = fmaf(acr, cr, rq1); rq2 = fmaf(acw, cw, rq2);
            #pragma unroll
            for (int q = 0; q < 4; q++) {
                X1[q] = fmaf(acr, p8[q], X1[q]);
                X2[q] = fmaf(acw, p8[q], X2[q]);
            }
        }
    }

    float* o = g0 + (size_t)(cta * 10 + w) * 69 * 32 + i;
    if (!ph) {
        #pragma unroll
        for (int f = 0; f < 8; f++)  o[f * 32] = aP[f];
        #pragma unroll
        for (int f = 0; f < 20; f++) o[(16 + f) * 32] = G[f];
        o[56 * 32] = ra;
        o[57 * 32] = rc1; o[58 * 32] = rc2;
        o[59 * 32] = rq1; o[60 * 32] = rq2;
        #pragma unroll
        for (int f = 0; f < 4; f++) { o[(61 + f) * 32] = X1[f]; o[(65 + f) * 32] = X2[f]; }
    } else {
        #pragma unroll
        for (int f = 0; f < 8; f++)  o[(8 + f) * 32] = aP[f];
        #pragma unroll
        for (int f = 0; f < 20; f++) o[(36 + f) * 32] = G[f];
    }
}

// ---------------- pass 0 stats ----------------
__global__ __launch_bounds__(320, 1)
void stats0_kernel(const float* __restrict__ wt,
                   const float* __restrict__ beta_v,
                   const float* __restrict__ beta_a)
{
    __shared__ float sm[32][72];
    const int b = blockIdx.x, tid = threadIdx.x;

    for (int t = tid; t < 32 * 69; t += 320) {
        const int i = t / 69, f = t - i * 69;
        const bool ph0 = (f < 8) || (f >= 16 && f < 36) || (f >= 56);
        const int ww0 = ph0 ? 0 : 5;
        float s = 0.f;
        #pragma unroll
        for (int qq = 0; qq < 4; qq++) {
            const size_t base = (size_t)(((b * 4 + qq) * 10 + ww0)) * 69 * 32 + f * 32 + i;
            #pragma unroll
            for (int ww = 0; ww < 5; ww++) s += g0[base + (size_t)ww * 69 * 32];
        }
        sm[i][f] = s;
    }
    __syncthreads();

    if (tid < 160) {
        const int c = tid >> 4, d = tid & 15, p = d >> 2, r = d & 3;
        float RA = 0.f, RC = 0.f, RQ = 0.f, Sv = 0.f, Sv2 = 0.f, Cr = 0.f;
        for (int i = 0; i < 32; i++) {
            const float* g = sm[i];
            const float* wr = wt + (i * CCL + c) * 16;
            const float W0 = wr[0*4+r], W1 = wr[1*4+r], W2 = wr[2*4+r], W3 = wr[3*4+r];
            const float* ap = g + p * 4;
            Sv += ap[0]*W0 + ap[1]*W1 + ap[2]*W2 + ap[3]*W3;
            const float* Gp = g + 16 + p * 10;
            Sv2 += W0*W0*Gp[0] + W1*W1*Gp[4] + W2*W2*Gp[7] + W3*W3*Gp[9]
                 + 2.f*(W0*W1*Gp[1] + W0*W2*Gp[2] + W0*W3*Gp[3]
                      + W1*W2*Gp[5] + W1*W3*Gp[6] + W2*W3*Gp[8]);
            RA += g[56];
            if (d == 0) { RC += g[57]; RQ += g[59]; Cr += W0*g[61]+W1*g[62]+W2*g[63]+W3*g[64]; }
            else if (d == 1) { RC += g[58]; RQ += g[60]; Cr += W0*g[65]+W1*g[66]+W2*g[67]+W3*g[68]; }
        }
        float coordm = (d == 0 || d == 1) ? RC : 0.f;
        float coordv = (d == 0 || d == 1) ? (2.f * Cr + RQ) : 0.f;
        float mean = (Sv + coordm) / RA;
        float var  = fmaxf((Sv2 + coordv) / RA - mean * mean, 0.f);
        float lg   = __logf(sqrtf(var) + EPSf);
        float rr_sum = RA * 0.1f;
        float cost = (beta_v[c] + lg) * rr_sum, lgs = lg;
        #pragma unroll
        for (int off = 8; off; off >>= 1) {
            cost += __shfl_xor_sync(0xffffffffu, cost, off, 16);
            lgs  += __shfl_xor_sync(0xffffffffu, lgs,  off, 16);
        }
        float oact = 1.f / (1.f + __expf(-(beta_a[c] - cost)));   // invT = 1
        float siv  = sqrtf(L2E / (2.f * var + EPSf));
        float* st = g_stats + (b * CCL + c) * 34;
        st[d]      = -mean * siv;
        st[16 + d] = siv;
        if (d == 0) st[32] = (__logf(oact + EPSf) - lgs) * L2E;
    }
}

// ---------------- routing passes 1 and 2 (R6 structure) ----------------
template<int IT>
__global__ __launch_bounds__(320, 2)
void accum_kernel(const float* __restrict__ pose,
                  const float* __restrict__ act,
                  const float* __restrict__ wt,
                  const float* __restrict__ beta_v,
                  const float* __restrict__ beta_a,
                  float* __restrict__ out)
{
    __shared__ float4 s_tile[2][128];
    __shared__ float  s_act[2][32];
    __shared__ float  s_zz[2][320];                    // [buf][c*32 + i], conflict-free
    __shared__ __align__(16) float s_stat[CCL][8][4];  // per pair j: nms0,nms1,siv0,siv1
    __shared__ float  s_cst[CCL];
    __shared__ float2 s_coord[49];
    __shared__ int    s_last;

    const int cta = blockIdx.x, b = cta >> 2, sl = cta & 3;
    const int tid = threadIdx.x, c = tid >> 5, lane = tid & 31;
    const int s0 = sl * 49;
    const int czz = c * 32;

    // ---- stats into smem ----
    if (tid < 160) {
        const int cc = tid >> 4, d = tid & 15;
        float nmsv, sivv, cstv = 0.f;
        if (IT == 1) {
            const float* st = g_stats + (b * CCL + cc) * 34;
            nmsv = st[d]; sivv = st[16 + d];
            if (d == 0) cstv = st[32];
        } else {
            float rsum0 = 0.f, sva = 0.f, sv2a = 0.f;
            #pragma unroll
            for (int q = 0; q < 4; q++) {
                const float* p = g_partial + ((b * 4 + q) * CCL + cc) * 34;
                rsum0 += p[0]; sva += p[1 + d]; sv2a += p[17 + d];
            }
            float mean = sva / rsum0;
            float var  = fmaxf(sv2a / rsum0 - mean * mean, 0.f);
            float lg   = __logf(sqrtf(var) + EPSf);
            float cost = (beta_v[cc] + lg) * rsum0, lgs = lg;
            #pragma unroll
            for (int off = 8; off; off >>= 1) {
                cost += __shfl_xor_sync(0xffffffffu, cost, off, 16);
                lgs  += __shfl_xor_sync(0xffffffffu, lgs,  off, 16);
            }
            float oact = 1.f / (1.f + __expf(-2.0f * (beta_a[cc] - cost)));  // invT = 2
            sivv = sqrtf(L2E / (2.f * var + EPSf));
            nmsv = -mean * sivv;
            if (d == 0) cstv = (__logf(oact + EPSf) - lgs) * L2E;
        }
        s_stat[cc][d >> 1][d & 1]       = nmsv;
        s_stat[cc][d >> 1][2 + (d & 1)] = sivv;
        if (d == 0) s_cst[cc] = cstv;
    } else if (tid >= 256 && tid < 305) {
        const int s = s0 + (tid - 256);
        const int h = s / 14, wx = s - h * 14;
        s_coord[tid - 256] = make_float2((h + 0.5f) * (1.0f/14.0f), (wx + 0.5f) * (1.0f/14.0f));
    }

    // ---- per-warp constants ----
    u64 W2[4][2];
    {
        const float* wr = wt + (lane * CCL + c) * 16;
        #pragma unroll
        for (int q = 0; q < 4; q++) {
            W2[q][0] = pack2(wr[q*4+0], wr[q*4+1]);
            W2[q][1] = pack2(wr[q*4+2], wr[q*4+3]);
        }
    }

    // loop-invariant swizzled read indices (float4 granularity)
    int sxp[4];
    #pragma unroll
    for (int p = 0; p < 4; p++) {
        const int idx = lane * 4 + p;
        sxp[p] = idx ^ ((idx >> 3) & 7);
    }
    // loop-invariant swizzled STS index (float2 granularity)
    const int idx4w = tid >> 1;
    const int sx2w  = (idx4w ^ ((idx4w >> 3) & 7)) * 2 + (tid & 1);

    u64 sv[8], sv2[8];
    #pragma unroll
    for (int j = 0; j < 8; j++) { sv[j] = 0ULL; sv2[j] = 0ULL; }
    float rsum = 0.f;

    const float2* pose2 = reinterpret_cast<const float2*>(pose);
    const size_t nb0 = ((size_t)(b * SSQ) + s0) * II;

    // preload tile 0 (float2 spread: warps 0-7 pose, warp 8 act)
    {
        float2* tile2 = reinterpret_cast<float2*>(&s_tile[0][0]);
        if (tid < 256)      tile2[sx2w] = pose2[nb0 * 8 + tid];
        else if (tid < 288) s_act[0][tid - 256] = act[nb0 + (tid - 256)];
    }
    __syncthreads();

    const float cstc = s_cst[c];
    const unsigned stat_base = (unsigned)__cvta_generic_to_shared(&s_stat[c][0][0]);

    for (int k = 0; k < 49; k++) {
        const int cur = k & 1, nxt = cur ^ 1;

        float2 pf; float pa;
        const bool doPf = (k < 48);
        if (doPf) {
            const size_t nbn = nb0 + (size_t)(k + 1) * II;
            if (tid < 256)      pf = pose2[nbn * 8 + tid];
            else if (tid < 288) pa = act[nbn + (tid - 256)];
        }

        // pose row + activation (both pre-barrier; buffers overwritten next iter)
        float p16[16];
        #pragma unroll
        for (int q = 0; q < 4; q++) {
            float4 t = s_tile[cur][sxp[q]];
            p16[q*4+0] = t.x; p16[q*4+1] = t.y; p16[q*4+2] = t.z; p16[q*4+3] = t.w;
        }
        const float a = s_act[cur][lane];

        // votes, r-paired; coords folded into init of pair (d0,d1)
        const float2 cc2 = s_coord[k];
        u64 v2[8];
        v2[0] = pack2(cc2.x, cc2.y);
        #pragma unroll
        for (int j = 1; j < 8; j++) v2[j] = 0ULL;
        #pragma unroll
        for (int p = 0; p < 4; p++) {
            #pragma unroll
            for (int q = 0; q < 4; q++) {
                const u64 pp = pack2(p16[p*4+q], p16[p*4+q]);
                v2[p*2+0] = fma2(pp, W2[q][0], v2[p*2+0]);
                v2[p*2+1] = fma2(pp, W2[q][1], v2[p*2+1]);
            }
        }

        // zz (log2): cst - sum ((v-m)*siv)^2 ; stats from broadcast smem
        u64 az0 = 0ULL, az1 = 0ULL;
        #pragma unroll
        for (int j = 0; j < 8; j++) {
            u64 nm, sviv;
            asm volatile("ld.shared.v2.b64 {%0,%1},[%2];"
                         : "=l"(nm), "=l"(sviv) : "r"(stat_base + 16u * j));
            u64 t = fma2(v2[j], sviv, nm);
            if (j & 1) az1 = fma2(t, t, az1);
            else       az0 = fma2(t, t, az0);
        }
        float l0, h0, l1, h1;
        unpack2(az0, l0, h0); unpack2(az1, l1, h1);
        const float zc = cstc - ((l0 + l1) + (h0 + h1));   // kept in register
        s_zz[cur][czz + lane] = zc;                         // 1-wf transposed store

        if (doPf) {
            float2* tile2 = reinterpret_cast<float2*>(&s_tile[nxt][0]);
            if (tid < 256)      tile2[sx2w] = pf;
            else if (tid < 288) s_act[nxt][tid - 256] = pa;
        }
        __syncthreads();   // zz visible + next tile staged

        // self-shifted softmax over classes (conflict-free reads)
        const float* zr = &s_zz[cur][lane];
        float Z0 = 0.f, Z1 = 0.f;
        #pragma unroll
        for (int j = 0; j < 10; j++) {
            float e = ex2f(zr[j * 32] - zc);
            if (j & 1) Z1 += e; else Z0 += e;
        }
        const float rrp = __fdividef(a, Z0 + Z1);

        rsum += rrp;
        const u64 rr2 = pack2(rrp, rrp);
        #pragma unroll
        for (int j = 0; j < 8; j++) {
            const u64 rv = mul2(rr2, v2[j]);
            sv[j]  = add2(sv[j], rv);
            sv2[j] = fma2(rv, v2[j], sv2[j]);
        }
    }

    // reduce over the 32 lanes (capsule i)
    #pragma unroll
    for (int off = 16; off; off >>= 1) {
        rsum += __shfl_xor_sync(0xffffffffu, rsum, off);
        #pragma unroll
        for (int j = 0; j < 8; j++) {
            sv[j]  = add2(sv[j],  __shfl_xor_sync(0xffffffffu, sv[j],  off));
            sv2[j] = add2(sv2[j], __shfl_xor_sync(0xffffffffu, sv2[j], off));
        }
    }
    if (lane == 0) {
        float* o = g_partial + (cta * CCL + c) * 34;
        o[0] = rsum;
        #pragma unroll
        for (int j = 0; j < 8; j++) {
            float lo, hi;
            unpack2(sv[j],  lo, hi); o[1  + 2*j] = lo; o[2  + 2*j] = hi;
            unpack2(sv2[j], lo, hi); o[17 + 2*j] = lo; o[18 + 2*j] = hi;
        }
    }

    // ---- IT==2: fused finalize, last CTA per batch ----
    if (IT == 2) {
        __syncthreads();
        if (tid == 0) {
            __threadfence();
            s_last = (atomicAdd(&g_cnt[b], 1) == 3);
        }
        __syncthreads();
        if (s_last) {
            if (tid == 0) g_cnt[b] = 0;           // reset for next graph replay
            if (tid < 160) {
                const int cc = tid >> 4, d = tid & 15;
                float rs = 0.f, svf = 0.f, sv2f = 0.f;
                #pragma unroll
                for (int q = 0; q < 4; q++) {
                    const float* p = g_partial + ((b * 4 + q) * CCL + cc) * 34;
                    rs += p[0]; svf += p[1 + d]; sv2f += p[17 + d];
                }
                float mean = svf / rs;
                float var  = fmaxf(sv2f / rs - mean * mean, 0.f);
                float lg   = __logf(sqrtf(var) + EPSf);
                float cost = (beta_v[cc] + lg) * rs;
                #pragma unroll
                for (int off = 8; off; off >>= 1)
                    cost += __shfl_xor_sync(0xffffffffu, cost, off, 16);
                float oact = 1.f / (1.f + __expf(-3.0f * (beta_a[cc] - cost)));  // invT = 3
                out[(b * CCL + cc) * 16 + d] = mean;
                if (d == 0) out[BB * CCL * 16 + b * CCL + cc] = oact;
            }
        }
    }
}

extern "C" void kernel_launch(void* const* d_in, const int* in_sizes, int n_in,
                              void* d_out, int out_size)
{
    const float* pose = (const float*)d_in[0];
    const float* act  = (const float*)d_in[1];
    const float* w    = (const float*)d_in[2];
    const float* bv   = (const float*)d_in[3];
    const float* ba   = (const float*)d_in[4];
    float* out = (float*)d_out;

    pass0_kernel <<<256, 320>>>(pose, act);
    stats0_kernel<<<64, 320>>>(w, bv, ba);
    accum_kernel<1><<<256, 320>>>(pose, act, w, bv, ba, out);
    accum_kernel<2><<<256, 320>>>(pose, act, w, bv, ba, out);
}